// round 2
// baseline (speedup 1.0000x reference)
#include <cuda_runtime.h>
#include <cuda_bf16.h>
#include <mma.h>
#include <type_traits>

using namespace nvcuda;

// B=8, S=2048, D_MODEL=1024, HD=1024, MT = B*S = 16384
#define MT_TOK 16384
#define DMODEL 1024
#define SEQ 2048
#define NBATCH 8

// ---------------------------------------------------------------------------
// Scratch (device globals: allocation-free rule)
// ---------------------------------------------------------------------------
__device__ float g_qh[16777216];      // [8,2048,1024]  reused for attn_out
__device__ float g_kh[16777216];
__device__ float g_vh[16777216];
__device__ float g_attn[16777216];
__device__ float g_scores[33554432];  // [8,2048,2048]

// ---------------------------------------------------------------------------
// cp.async helpers (16B)
// ---------------------------------------------------------------------------
__device__ __forceinline__ void cp_async16(void* smem_ptr, const void* gmem_ptr)
{
    unsigned s = (unsigned)__cvta_generic_to_shared(smem_ptr);
    asm volatile("cp.async.cg.shared.global [%0], [%1], 16;\n" :: "r"(s), "l"(gmem_ptr));
}
__device__ __forceinline__ void cp_commit()
{
    asm volatile("cp.async.commit_group;\n" ::: "memory");
}
template <int N>
__device__ __forceinline__ void cp_wait()
{
    asm volatile("cp.async.wait_group %0;\n" :: "n"(N) : "memory");
}

// ---------------------------------------------------------------------------
// TF32 WMMA GEMM, 2-stage cp.async pipeline:
//   C[M,N] = scale * (A[M,K] @ op(B)) + bias[N]
//   BT=1: B is [N,K] row-major (NT)    BT=0: B is [K,N] row-major (NN)
// Block tile 128x128x32, 8 warps, warp tile 64x32 of m16n16k8 tf32.
// M%128==0, N%128==0, K%32==0 hold for every call here.
// ---------------------------------------------------------------------------
template <int BT>
__global__ void __launch_bounds__(256) gemm_tf32(
    const float* __restrict__ A, const float* __restrict__ Bm,
    float* __restrict__ C, int M, int N, int K,
    long long sA, long long sB, long long sC,
    const float* __restrict__ bias, float scale)
{
    constexpr int LDA = 36;
    constexpr int LDB = BT ? 36 : 132;
    constexpr int BSZ = BT ? (128 * 36) : (32 * 132);

    __shared__ float As[2][128 * 36];
    __shared__ float Bs[2][BSZ];
    __shared__ float Ctmp[8][16 * 16];

    const int tid  = threadIdx.x;
    const int warp = tid >> 5;
    const int lane = tid & 31;
    const int wm   = warp & 1;   // 2 warps over M (64 rows each)
    const int wn   = warp >> 1;  // 4 warps over N (32 cols each)

    const long long bz = blockIdx.z;
    A  += bz * sA;
    Bm += bz * sB;
    C  += bz * sC;

    const int tm = blockIdx.y * 128;
    const int tn = blockIdx.x * 128;

    // Per-thread load coordinates (8 x 16B per thread per tile side)
    const int arow = tid >> 3;          // 0..127
    const int ac4  = (tid & 7) * 4;     // 0..28
    const int brow = BT ? arow : (tid >> 5);
    const int bc4  = BT ? ac4 : ((tid & 31) * 4);

    const float* Aorig = A + (size_t)(tm + arow) * K + ac4;
    const float* Borig = BT ? (Bm + (size_t)(tn + brow) * K + bc4)
                            : (Bm + (size_t)brow * N + tn + bc4);

    auto load_stage = [&](int buf, int k0) {
        // A: 128x32, 4 x 16B rounds (row stride 32)
#pragma unroll
        for (int it = 0; it < 4; it++)
            cp_async16(&As[buf][(arow + it * 32) * LDA + ac4],
                       Aorig + (size_t)(it * 32) * K + k0);
        if (BT) {
#pragma unroll
            for (int it = 0; it < 4; it++)
                cp_async16(&Bs[buf][(brow + it * 32) * LDB + bc4],
                           Borig + (size_t)(it * 32) * K + k0);
        } else {
#pragma unroll
            for (int it = 0; it < 4; it++)
                cp_async16(&Bs[buf][(brow + it * 8) * LDB + bc4],
                           Borig + (size_t)(k0 + it * 8) * N);
        }
        cp_commit();
    };

    using BLayout = typename std::conditional<(BT != 0), wmma::col_major, wmma::row_major>::type;

    wmma::fragment<wmma::accumulator, 16, 16, 8, float> fc[4][2];
#pragma unroll
    for (int i = 0; i < 4; i++)
#pragma unroll
        for (int j = 0; j < 2; j++) wmma::fill_fragment(fc[i][j], 0.0f);

    const int nk = K >> 5;
    load_stage(0, 0);

    for (int kt = 0; kt < nk; kt++) {
        if (kt + 1 < nk) load_stage((kt + 1) & 1, (kt + 1) << 5);
        if (kt + 1 < nk) cp_wait<1>(); else cp_wait<0>();
        __syncthreads();

        const float* as = As[kt & 1];
        const float* bs = Bs[kt & 1];
#pragma unroll
        for (int kk = 0; kk < 32; kk += 8) {
            wmma::fragment<wmma::matrix_a, 16, 16, 8, wmma::precision::tf32, wmma::row_major> fa[4];
            wmma::fragment<wmma::matrix_b, 16, 16, 8, wmma::precision::tf32, BLayout> fb[2];
#pragma unroll
            for (int i = 0; i < 4; i++) {
                wmma::load_matrix_sync(fa[i], &as[(wm * 64 + i * 16) * LDA + kk], LDA);
#pragma unroll
                for (int t = 0; t < fa[i].num_elements; t++)
                    fa[i].x[t] = wmma::__float_to_tf32(fa[i].x[t]);
            }
#pragma unroll
            for (int j = 0; j < 2; j++) {
                if (BT)
                    wmma::load_matrix_sync(fb[j], &bs[(wn * 32 + j * 16) * LDB + kk], LDB);
                else
                    wmma::load_matrix_sync(fb[j], &bs[kk * LDB + wn * 32 + j * 16], LDB);
#pragma unroll
                for (int t = 0; t < fb[j].num_elements; t++)
                    fb[j].x[t] = wmma::__float_to_tf32(fb[j].x[t]);
            }
#pragma unroll
            for (int i = 0; i < 4; i++)
#pragma unroll
                for (int j = 0; j < 2; j++)
                    wmma::mma_sync(fc[i][j], fa[i], fb[j], fc[i][j]);
        }
        __syncthreads();   // compute done before this buffer is refilled
    }

    // ---- epilogue ----
    if (bias == nullptr) {
        // direct fragment -> global (scale folded in)
#pragma unroll
        for (int i = 0; i < 4; i++)
#pragma unroll
            for (int j = 0; j < 2; j++) {
#pragma unroll
                for (int t = 0; t < fc[i][j].num_elements; t++) fc[i][j].x[t] *= scale;
                int gr = tm + wm * 64 + i * 16;
                int gc = tn + wn * 32 + j * 16;
                wmma::store_matrix_sync(C + (size_t)gr * N + gc, fc[i][j], N,
                                        wmma::mem_row_major);
            }
    } else {
#pragma unroll
        for (int i = 0; i < 4; i++) {
#pragma unroll
            for (int j = 0; j < 2; j++) {
#pragma unroll
                for (int t = 0; t < fc[i][j].num_elements; t++) fc[i][j].x[t] *= scale;
                wmma::store_matrix_sync(&Ctmp[warp][0], fc[i][j], 16, wmma::mem_row_major);
                __syncwarp();
                int r  = lane >> 1;
                int cb = (lane & 1) * 8;
                int gr = tm + wm * 64 + i * 16 + r;
                int gc = tn + wn * 32 + j * 16 + cb;
                float* cp = C + (size_t)gr * N + gc;
#pragma unroll
                for (int e = 0; e < 8; e++)
                    cp[e] = Ctmp[warp][r * 16 + cb + e] + __ldg(&bias[gc + e]);
                __syncwarp();
            }
        }
    }
}

// ---------------------------------------------------------------------------
// Block reduction helpers
// ---------------------------------------------------------------------------
__device__ __forceinline__ float block_reduce_max(float v, float* sred)
{
    int lane = threadIdx.x & 31, warp = threadIdx.x >> 5;
#pragma unroll
    for (int o = 16; o > 0; o >>= 1) v = fmaxf(v, __shfl_xor_sync(0xffffffffu, v, o));
    if (lane == 0) sred[warp] = v;
    __syncthreads();
    if (warp == 0) {
        v = (lane < 8) ? sred[lane] : -3.402823e38f;
#pragma unroll
        for (int o = 4; o > 0; o >>= 1) v = fmaxf(v, __shfl_xor_sync(0xffffffffu, v, o));
        if (lane == 0) sred[0] = v;
    }
    __syncthreads();
    return sred[0];
}

__device__ __forceinline__ float block_reduce_sum(float v, float* sred)
{
    int lane = threadIdx.x & 31, warp = threadIdx.x >> 5;
#pragma unroll
    for (int o = 16; o > 0; o >>= 1) v += __shfl_xor_sync(0xffffffffu, v, o);
    if (lane == 0) sred[warp] = v;
    __syncthreads();
    if (warp == 0) {
        v = (lane < 8) ? sred[lane] : 0.0f;
#pragma unroll
        for (int o = 4; o > 0; o >>= 1) v += __shfl_xor_sync(0xffffffffu, v, o);
        if (lane == 0) sred[0] = v;
    }
    __syncthreads();
    return sred[0];
}

// ---------------------------------------------------------------------------
// Softmax over last dim (2048), in place. 1 read + 1 write per element.
// ---------------------------------------------------------------------------
__global__ void __launch_bounds__(256) softmax_kernel(float* __restrict__ P)
{
    __shared__ float sred[32];
    size_t row = blockIdx.x;
    float4* p  = reinterpret_cast<float4*>(P + row * (size_t)SEQ);
    int tid    = threadIdx.x;

    float4 a = p[tid];
    float4 b = p[tid + 256];

    float m = fmaxf(fmaxf(fmaxf(a.x, a.y), fmaxf(a.z, a.w)),
                    fmaxf(fmaxf(b.x, b.y), fmaxf(b.z, b.w)));
    m = block_reduce_max(m, sred);

    a.x = __expf(a.x - m); a.y = __expf(a.y - m);
    a.z = __expf(a.z - m); a.w = __expf(a.w - m);
    b.x = __expf(b.x - m); b.y = __expf(b.y - m);
    b.z = __expf(b.z - m); b.w = __expf(b.w - m);

    float s = (a.x + a.y + a.z + a.w) + (b.x + b.y + b.z + b.w);
    __syncthreads();
    s = block_reduce_sum(s, sred);

    float inv = 1.0f / s;
    a.x *= inv; a.y *= inv; a.z *= inv; a.w *= inv;
    b.x *= inv; b.y *= inv; b.z *= inv; b.w *= inv;
    p[tid]       = a;
    p[tid + 256] = b;
}

// ---------------------------------------------------------------------------
// Residual + LayerNorm: out = LN(q + attn_out) * gamma + beta
// ---------------------------------------------------------------------------
__global__ void __launch_bounds__(256) ln_kernel(
    const float* __restrict__ q, const float* __restrict__ ao,
    const float* __restrict__ gamma, const float* __restrict__ beta,
    float* __restrict__ out)
{
    __shared__ float sred[32];
    size_t row = blockIdx.x;
    int tid    = threadIdx.x;

    const float4 qv = reinterpret_cast<const float4*>(q  + row * (size_t)DMODEL)[tid];
    const float4 av = reinterpret_cast<const float4*>(ao + row * (size_t)DMODEL)[tid];

    float x0 = qv.x + av.x, x1 = qv.y + av.y, x2 = qv.z + av.z, x3 = qv.w + av.w;

    float s = x0 + x1 + x2 + x3;
    s = block_reduce_sum(s, sred);
    float mu = s * (1.0f / DMODEL);

    float d0 = x0 - mu, d1 = x1 - mu, d2 = x2 - mu, d3 = x3 - mu;
    float s2 = d0 * d0 + d1 * d1 + d2 * d2 + d3 * d3;
    __syncthreads();
    s2 = block_reduce_sum(s2, sred);
    float rs = rsqrtf(s2 * (1.0f / DMODEL) + 1e-5f);

    const float4 gv = reinterpret_cast<const float4*>(gamma)[tid];
    const float4 bv = reinterpret_cast<const float4*>(beta)[tid];
    float4 o;
    o.x = d0 * rs * gv.x + bv.x;
    o.y = d1 * rs * gv.y + bv.y;
    o.z = d2 * rs * gv.z + bv.z;
    o.w = d3 * rs * gv.w + bv.w;
    reinterpret_cast<float4*>(out + row * (size_t)DMODEL)[tid] = o;
}

// ---------------------------------------------------------------------------
// Launch
// ---------------------------------------------------------------------------
extern "C" void kernel_launch(void* const* d_in, const int* in_sizes, int n_in,
                              void* d_out, int out_size)
{
    const float* q     = (const float*)d_in[0];
    const float* k     = (const float*)d_in[1];
    const float* v     = (const float*)d_in[2];
    const float* Wq    = (const float*)d_in[3];
    const float* Wk    = (const float*)d_in[4];
    const float* bk    = (const float*)d_in[5];
    const float* Wv    = (const float*)d_in[6];
    const float* bv    = (const float*)d_in[7];
    const float* Wo    = (const float*)d_in[8];
    const float* bo    = (const float*)d_in[9];
    const float* gamma = (const float*)d_in[10];
    const float* beta  = (const float*)d_in[11];
    float* out = (float*)d_out;

    float *qh, *kh, *vh, *attn, *scores;
    cudaGetSymbolAddress((void**)&qh,     g_qh);
    cudaGetSymbolAddress((void**)&kh,     g_kh);
    cudaGetSymbolAddress((void**)&vh,     g_vh);
    cudaGetSymbolAddress((void**)&attn,   g_attn);
    cudaGetSymbolAddress((void**)&scores, g_scores);

    dim3 blk(256);
    const float scale = 0.125f;  // 1/sqrt(64)

    // Projections: [16384,1024] @ [1024,1024]^T
    gemm_tf32<1><<<dim3(8, 128, 1), blk>>>(q, Wq, qh, MT_TOK, DMODEL, DMODEL,
                                           0, 0, 0, nullptr, scale);
    gemm_tf32<1><<<dim3(8, 128, 1), blk>>>(k, Wk, kh, MT_TOK, DMODEL, DMODEL,
                                           0, 0, 0, bk, 1.0f);
    gemm_tf32<1><<<dim3(8, 128, 1), blk>>>(v, Wv, vh, MT_TOK, DMODEL, DMODEL,
                                           0, 0, 0, bv, 1.0f);

    // scores[b] = qh[b] @ kh[b]^T  (batched NT, M=N=2048, K=1024)
    gemm_tf32<1><<<dim3(16, 16, NBATCH), blk>>>(
        qh, kh, scores, SEQ, SEQ, DMODEL,
        (long long)SEQ * DMODEL, (long long)SEQ * DMODEL,
        (long long)SEQ * SEQ, nullptr, 1.0f);

    // softmax rows (in place)
    softmax_kernel<<<MT_TOK, 256>>>(scores);

    // attn[b] = probs[b] @ vh[b]  (batched NN, M=2048, N=1024, K=2048)
    gemm_tf32<0><<<dim3(8, 16, NBATCH), blk>>>(
        scores, vh, attn, SEQ, DMODEL, SEQ,
        (long long)SEQ * SEQ, (long long)SEQ * DMODEL,
        (long long)SEQ * DMODEL, nullptr, 1.0f);

    // out-proj (+bo) into qh (reused as attn_out scratch)
    gemm_tf32<1><<<dim3(8, 128, 1), blk>>>(attn, Wo, qh, MT_TOK, DMODEL, DMODEL,
                                           0, 0, 0, bo, 1.0f);

    // residual + LN -> d_out
    ln_kernel<<<MT_TOK, 256>>>(q, qh, gamma, beta, out);
}

// round 6
// speedup vs baseline: 3.2665x; 3.2665x over previous
#include <cuda_runtime.h>
#include <cuda_bf16.h>
#include <mma.h>
#include <type_traits>
#include <cstdint>

using namespace nvcuda;

#define MT_TOK 16384
#define DMODEL 1024
#define SEQ    2048
#define NBATCH 8

// ---------------------------------------------------------------------------
// Scratch (device globals; allocation-free rule)
// ---------------------------------------------------------------------------
__device__ __nv_bfloat16 g_qb [MT_TOK * DMODEL];
__device__ __nv_bfloat16 g_kb [MT_TOK * DMODEL];
__device__ __nv_bfloat16 g_vb [MT_TOK * DMODEL];
__device__ __nv_bfloat16 g_Wqb[DMODEL * DMODEL];
__device__ __nv_bfloat16 g_Wkb[DMODEL * DMODEL];
__device__ __nv_bfloat16 g_Wvb[DMODEL * DMODEL];
__device__ __nv_bfloat16 g_Wob[DMODEL * DMODEL];
__device__ __nv_bfloat16 g_qh [MT_TOK * DMODEL];   // q-proj out (pre-scaled)
__device__ __nv_bfloat16 g_kh [MT_TOK * DMODEL];   // k-proj out (+bk)
__device__ __nv_bfloat16 g_vh [MT_TOK * DMODEL];   // v-proj out (+bv)
__device__ __nv_bfloat16 g_attn[MT_TOK * DMODEL];  // P@V out
__device__ float         g_scores[(size_t)NBATCH * SEQ * SEQ]; // fp32 scores; bf16 probs in place
__device__ float         g_attnout[MT_TOK * DMODEL];

__device__ __forceinline__ uint32_t pack_bf2(float a, float b)
{
    __nv_bfloat162 h = __floats2bfloat162_rn(a, b);
    return *reinterpret_cast<uint32_t*>(&h);
}

// ---------------------------------------------------------------------------
// cp.async helpers
// ---------------------------------------------------------------------------
__device__ __forceinline__ void cp_async16(void* smem_ptr, const void* gmem_ptr)
{
    unsigned s = (unsigned)__cvta_generic_to_shared(smem_ptr);
    asm volatile("cp.async.cg.shared.global [%0], [%1], 16;\n" :: "r"(s), "l"(gmem_ptr));
}
__device__ __forceinline__ void cp_commit()
{
    asm volatile("cp.async.commit_group;\n" ::: "memory");
}
template <int N>
__device__ __forceinline__ void cp_wait()
{
    asm volatile("cp.async.wait_group %0;\n" :: "n"(N) : "memory");
}

// ---------------------------------------------------------------------------
// bf16 WMMA GEMM (m16n16k16, fp32 accum), 2-stage cp.async pipeline:
//   C[M,N] = scale * (A[M,K] @ op(B)) + bias[N]
//   BT=1: B is [N,K] row-major (NT)    BT=0: B is [K,N] row-major (NN)
//   OutT: float or __nv_bfloat16.
// Block tile 128x128x32, 8 warps (warp tile 64x32). M%128==N%128==0, K%32==0.
// ---------------------------------------------------------------------------
template <int BT, typename OutT>
__global__ void __launch_bounds__(256, 2) gemm_bf16(
    const __nv_bfloat16* __restrict__ A, const __nv_bfloat16* __restrict__ Bm,
    OutT* __restrict__ C, int M, int N, int K, int lda, int ldb,
    long long sA, long long sB, long long sC,
    const float* __restrict__ bias, float scale)
{
    constexpr int LDA = 40;                  // 32 + 8 pad, 80B rows (16B mult)
    constexpr int LDB = BT ? 40 : 136;       // NN: 272B rows (16B mult)
    constexpr int BSZ = BT ? (128 * 40) : (32 * 136);

    __shared__ __align__(16) __nv_bfloat16 As[2][128 * 40];
    __shared__ __align__(16) __nv_bfloat16 Bs[2][BSZ];

    const int tid  = threadIdx.x;
    const int warp = tid >> 5;
    const int lane = tid & 31;
    const int wm   = warp & 1;   // 2 warps over M (64 rows)
    const int wn   = warp >> 1;  // 4 warps over N (32 cols)

    const long long bz = blockIdx.z;
    A  += bz * sA;
    Bm += bz * sB;
    C  += bz * sC;

    const int tm = blockIdx.y * 128;
    const int tn = blockIdx.x * 128;

    // A loads: 512 x 16B chunks (2/thread). row = idx>>2, c8 = (idx&3)*8
    const int ar  = tid >> 2;
    const int ac8 = (tid & 3) * 8;
    // B loads
    const int br  = BT ? ar : (tid >> 4);
    const int bc8 = BT ? ac8 : ((tid & 15) * 8);

    const __nv_bfloat16* Aor = A + (size_t)(tm + ar) * lda + ac8;
    const __nv_bfloat16* Bor = BT ? (Bm + (size_t)(tn + br) * ldb + bc8)
                                  : (Bm + (size_t)br * ldb + tn + bc8);

    auto load_stage = [&](int buf, int k0) {
#pragma unroll
        for (int it = 0; it < 2; it++)
            cp_async16(&As[buf][(ar + it * 64) * LDA + ac8],
                       Aor + (size_t)(it * 64) * lda + k0);
        if (BT) {
#pragma unroll
            for (int it = 0; it < 2; it++)
                cp_async16(&Bs[buf][(br + it * 64) * LDB + bc8],
                           Bor + (size_t)(it * 64) * ldb + k0);
        } else {
#pragma unroll
            for (int it = 0; it < 2; it++)
                cp_async16(&Bs[buf][(br + it * 16) * LDB + bc8],
                           Bor + (size_t)(k0 + it * 16) * ldb);
        }
        cp_commit();
    };

    using BLayout = typename std::conditional<(BT != 0), wmma::col_major, wmma::row_major>::type;

    wmma::fragment<wmma::accumulator, 16, 16, 16, float> fc[4][2];
#pragma unroll
    for (int i = 0; i < 4; i++)
#pragma unroll
        for (int j = 0; j < 2; j++) wmma::fill_fragment(fc[i][j], 0.0f);

    const int nk = K >> 5;
    load_stage(0, 0);

    for (int kt = 0; kt < nk; kt++) {
        if (kt + 1 < nk) load_stage((kt + 1) & 1, (kt + 1) << 5);
        if (kt + 1 < nk) cp_wait<1>(); else cp_wait<0>();
        __syncthreads();

        const __nv_bfloat16* as = As[kt & 1];
        const __nv_bfloat16* bs = Bs[kt & 1];
#pragma unroll
        for (int kk = 0; kk < 32; kk += 16) {
            wmma::fragment<wmma::matrix_a, 16, 16, 16, __nv_bfloat16, wmma::row_major> fa[4];
            wmma::fragment<wmma::matrix_b, 16, 16, 16, __nv_bfloat16, BLayout> fb[2];
#pragma unroll
            for (int i = 0; i < 4; i++)
                wmma::load_matrix_sync(fa[i], &as[(wm * 64 + i * 16) * LDA + kk], LDA);
#pragma unroll
            for (int j = 0; j < 2; j++) {
                if (BT)
                    wmma::load_matrix_sync(fb[j], &bs[(wn * 32 + j * 16) * LDB + kk], LDB);
                else
                    wmma::load_matrix_sync(fb[j], &bs[kk * LDB + wn * 32 + j * 16], LDB);
            }
#pragma unroll
            for (int i = 0; i < 4; i++)
#pragma unroll
                for (int j = 0; j < 2; j++)
                    wmma::mma_sync(fc[i][j], fa[i], fb[j], fc[i][j]);
        }
        __syncthreads();
    }

    // ---- epilogue ----
    constexpr bool OUT_F32 = std::is_same<OutT, float>::value;
    if (OUT_F32 && bias == nullptr) {
        // direct fragment -> global fp32
#pragma unroll
        for (int i = 0; i < 4; i++)
#pragma unroll
            for (int j = 0; j < 2; j++) {
#pragma unroll
                for (int t = 0; t < fc[i][j].num_elements; t++) fc[i][j].x[t] *= scale;
                int gr = tm + wm * 64 + i * 16;
                int gc = tn + wn * 32 + j * 16;
                wmma::store_matrix_sync((float*)C + (size_t)gr * N + gc, fc[i][j], N,
                                        wmma::mem_row_major);
            }
    } else {
        // bounce via smem (reuse As; dead after mainloop's final __syncthreads)
        float* ct = reinterpret_cast<float*>(&As[0][0]) + warp * 256;
#pragma unroll
        for (int i = 0; i < 4; i++) {
#pragma unroll
            for (int j = 0; j < 2; j++) {
#pragma unroll
                for (int t = 0; t < fc[i][j].num_elements; t++) fc[i][j].x[t] *= scale;
                wmma::store_matrix_sync(ct, fc[i][j], 16, wmma::mem_row_major);
                __syncwarp();
                int r  = lane >> 1;
                int cb = (lane & 1) * 8;
                int gr = tm + wm * 64 + i * 16 + r;
                int gc = tn + wn * 32 + j * 16 + cb;
                float v[8];
#pragma unroll
                for (int e = 0; e < 8; e++) {
                    v[e] = ct[r * 16 + cb + e];
                    if (bias) v[e] += __ldg(&bias[gc + e]);
                }
                if (OUT_F32) {
                    float* cp = (float*)C + (size_t)gr * N + gc;
                    *reinterpret_cast<float4*>(cp)     = make_float4(v[0], v[1], v[2], v[3]);
                    *reinterpret_cast<float4*>(cp + 4) = make_float4(v[4], v[5], v[6], v[7]);
                } else {
                    __nv_bfloat16* cp = (__nv_bfloat16*)C + (size_t)gr * N + gc;
                    uint4 u;
                    u.x = pack_bf2(v[0], v[1]); u.y = pack_bf2(v[2], v[3]);
                    u.z = pack_bf2(v[4], v[5]); u.w = pack_bf2(v[6], v[7]);
                    *reinterpret_cast<uint4*>(cp) = u;
                }
                __syncwarp();
            }
        }
    }
}

// ---------------------------------------------------------------------------
// fp32 -> bf16 conversion (8 elems/thread)
// ---------------------------------------------------------------------------
__global__ void __launch_bounds__(256) f2bf_kernel(const float* __restrict__ in,
                                                   __nv_bfloat16* __restrict__ out, int n)
{
    int i = (blockIdx.x * 256 + threadIdx.x) * 8;
    if (i >= n) return;
    float4 a = *reinterpret_cast<const float4*>(in + i);
    float4 b = *reinterpret_cast<const float4*>(in + i + 4);
    uint4 u;
    u.x = pack_bf2(a.x, a.y); u.y = pack_bf2(a.z, a.w);
    u.z = pack_bf2(b.x, b.y); u.w = pack_bf2(b.z, b.w);
    *reinterpret_cast<uint4*>(out + i) = u;
}

// ---------------------------------------------------------------------------
// reductions
// ---------------------------------------------------------------------------
__device__ __forceinline__ float block_reduce_max(float v, float* sred)
{
    int lane = threadIdx.x & 31, warp = threadIdx.x >> 5;
#pragma unroll
    for (int o = 16; o > 0; o >>= 1) v = fmaxf(v, __shfl_xor_sync(0xffffffffu, v, o));
    if (lane == 0) sred[warp] = v;
    __syncthreads();
    if (warp == 0) {
        v = (lane < 8) ? sred[lane] : -3.402823e38f;
#pragma unroll
        for (int o = 4; o > 0; o >>= 1) v = fmaxf(v, __shfl_xor_sync(0xffffffffu, v, o));
        if (lane == 0) sred[0] = v;
    }
    __syncthreads();
    return sred[0];
}
__device__ __forceinline__ float block_reduce_sum(float v, float* sred)
{
    int lane = threadIdx.x & 31, warp = threadIdx.x >> 5;
#pragma unroll
    for (int o = 16; o > 0; o >>= 1) v += __shfl_xor_sync(0xffffffffu, v, o);
    if (lane == 0) sred[warp] = v;
    __syncthreads();
    if (warp == 0) {
        v = (lane < 8) ? sred[lane] : 0.0f;
#pragma unroll
        for (int o = 4; o > 0; o >>= 1) v += __shfl_xor_sync(0xffffffffu, v, o);
        if (lane == 0) sred[0] = v;
    }
    __syncthreads();
    return sred[0];
}

// ---------------------------------------------------------------------------
// Softmax over 2048 fp32 -> bf16 probs in place (row stride preserved)
// ---------------------------------------------------------------------------
__global__ void __launch_bounds__(256) softmax_kernel(float* __restrict__ P)
{
    __shared__ float sred[32];
    size_t row = blockIdx.x;
    float4* p = reinterpret_cast<float4*>(P + row * (size_t)SEQ);
    int tid = threadIdx.x;

    float4 a = p[tid];
    float4 b = p[tid + 256];

    float m = fmaxf(fmaxf(fmaxf(a.x, a.y), fmaxf(a.z, a.w)),
                    fmaxf(fmaxf(b.x, b.y), fmaxf(b.z, b.w)));
    m = block_reduce_max(m, sred);

    a.x = __expf(a.x - m); a.y = __expf(a.y - m);
    a.z = __expf(a.z - m); a.w = __expf(a.w - m);
    b.x = __expf(b.x - m); b.y = __expf(b.y - m);
    b.z = __expf(b.z - m); b.w = __expf(b.w - m);

    float s = (a.x + a.y + a.z + a.w) + (b.x + b.y + b.z + b.w);
    __syncthreads();
    s = block_reduce_sum(s, sred);
    float inv = 1.0f / s;

    __nv_bfloat16* outp = reinterpret_cast<__nv_bfloat16*>(P) + row * (size_t)(2 * SEQ);
    uint2 ua, ub;
    ua.x = pack_bf2(a.x * inv, a.y * inv); ua.y = pack_bf2(a.z * inv, a.w * inv);
    ub.x = pack_bf2(b.x * inv, b.y * inv); ub.y = pack_bf2(b.z * inv, b.w * inv);
    *reinterpret_cast<uint2*>(outp + 4 * tid)        = ua;
    *reinterpret_cast<uint2*>(outp + 1024 + 4 * tid) = ub;
}

// ---------------------------------------------------------------------------
// Residual + LayerNorm
// ---------------------------------------------------------------------------
__global__ void __launch_bounds__(256) ln_kernel(
    const float* __restrict__ q, const float* __restrict__ ao,
    const float* __restrict__ gamma, const float* __restrict__ beta,
    float* __restrict__ out)
{
    __shared__ float sred[32];
    size_t row = blockIdx.x;
    int tid = threadIdx.x;

    const float4 qv = reinterpret_cast<const float4*>(q  + row * (size_t)DMODEL)[tid];
    const float4 av = reinterpret_cast<const float4*>(ao + row * (size_t)DMODEL)[tid];
    float x0 = qv.x + av.x, x1 = qv.y + av.y, x2 = qv.z + av.z, x3 = qv.w + av.w;

    float s = x0 + x1 + x2 + x3;
    s = block_reduce_sum(s, sred);
    float mu = s * (1.0f / DMODEL);

    float d0 = x0 - mu, d1 = x1 - mu, d2 = x2 - mu, d3 = x3 - mu;
    float s2 = d0 * d0 + d1 * d1 + d2 * d2 + d3 * d3;
    __syncthreads();
    s2 = block_reduce_sum(s2, sred);
    float rs = rsqrtf(s2 * (1.0f / DMODEL) + 1e-5f);

    const float4 gv = reinterpret_cast<const float4*>(gamma)[tid];
    const float4 bv = reinterpret_cast<const float4*>(beta)[tid];
    float4 o;
    o.x = d0 * rs * gv.x + bv.x;
    o.y = d1 * rs * gv.y + bv.y;
    o.z = d2 * rs * gv.z + bv.z;
    o.w = d3 * rs * gv.w + bv.w;
    reinterpret_cast<float4*>(out + row * (size_t)DMODEL)[tid] = o;
}

// ---------------------------------------------------------------------------
// Launch
// ---------------------------------------------------------------------------
extern "C" void kernel_launch(void* const* d_in, const int* in_sizes, int n_in,
                              void* d_out, int out_size)
{
    const float* q     = (const float*)d_in[0];
    const float* k     = (const float*)d_in[1];
    const float* v     = (const float*)d_in[2];
    const float* Wq    = (const float*)d_in[3];
    const float* Wk    = (const float*)d_in[4];
    const float* bk    = (const float*)d_in[5];
    const float* Wv    = (const float*)d_in[6];
    const float* bv    = (const float*)d_in[7];
    const float* Wo    = (const float*)d_in[8];
    const float* bo    = (const float*)d_in[9];
    const float* gamma = (const float*)d_in[10];
    const float* beta  = (const float*)d_in[11];
    float* out = (float*)d_out;

    __nv_bfloat16 *qb, *kb, *vb, *Wqb, *Wkb, *Wvb, *Wob, *qh, *kh, *vh, *attn;
    float *scores, *attnout;
    cudaGetSymbolAddress((void**)&qb,      g_qb);
    cudaGetSymbolAddress((void**)&kb,      g_kb);
    cudaGetSymbolAddress((void**)&vb,      g_vb);
    cudaGetSymbolAddress((void**)&Wqb,     g_Wqb);
    cudaGetSymbolAddress((void**)&Wkb,     g_Wkb);
    cudaGetSymbolAddress((void**)&Wvb,     g_Wvb);
    cudaGetSymbolAddress((void**)&Wob,     g_Wob);
    cudaGetSymbolAddress((void**)&qh,      g_qh);
    cudaGetSymbolAddress((void**)&kh,      g_kh);
    cudaGetSymbolAddress((void**)&vh,      g_vh);
    cudaGetSymbolAddress((void**)&attn,    g_attn);
    cudaGetSymbolAddress((void**)&scores,  g_scores);
    cudaGetSymbolAddress((void**)&attnout, g_attnout);

    // fp32 -> bf16 conversions
    f2bf_kernel<<<8192, 256>>>(q,  qb, MT_TOK * DMODEL);
    f2bf_kernel<<<8192, 256>>>(k,  kb, MT_TOK * DMODEL);
    f2bf_kernel<<<8192, 256>>>(v,  vb, MT_TOK * DMODEL);
    f2bf_kernel<<<512,  256>>>(Wq, Wqb, DMODEL * DMODEL);
    f2bf_kernel<<<512,  256>>>(Wk, Wkb, DMODEL * DMODEL);
    f2bf_kernel<<<512,  256>>>(Wv, Wvb, DMODEL * DMODEL);
    f2bf_kernel<<<512,  256>>>(Wo, Wob, DMODEL * DMODEL);

    dim3 blk(256);

    // projections (NT, bf16 out): [16384,1024] @ [1024,1024]^T
    gemm_bf16<1, __nv_bfloat16><<<dim3(8, 128, 1), blk>>>(
        qb, Wqb, qh, MT_TOK, DMODEL, DMODEL, DMODEL, DMODEL,
        0, 0, 0, nullptr, 0.125f);
    gemm_bf16<1, __nv_bfloat16><<<dim3(8, 128, 1), blk>>>(
        kb, Wkb, kh, MT_TOK, DMODEL, DMODEL, DMODEL, DMODEL,
        0, 0, 0, bk, 1.0f);
    gemm_bf16<1, __nv_bfloat16><<<dim3(8, 128, 1), blk>>>(
        vb, Wvb, vh, MT_TOK, DMODEL, DMODEL, DMODEL, DMODEL,
        0, 0, 0, bv, 1.0f);

    // scores[b] = qh[b] @ kh[b]^T -> fp32 (direct epilogue)
    gemm_bf16<1, float><<<dim3(16, 16, NBATCH), blk>>>(
        qh, kh, scores, SEQ, SEQ, DMODEL, DMODEL, DMODEL,
        (long long)SEQ * DMODEL, (long long)SEQ * DMODEL, (long long)SEQ * SEQ,
        nullptr, 1.0f);

    // softmax -> bf16 probs in place (row stride 4096 bf16)
    softmax_kernel<<<MT_TOK, 256>>>(scores);

    // attn[b] = probs[b] @ vh[b]  (NN, bf16 out)
    gemm_bf16<0, __nv_bfloat16><<<dim3(8, 16, NBATCH), blk>>>(
        (const __nv_bfloat16*)scores, vh, attn, SEQ, DMODEL, SEQ,
        2 * SEQ, DMODEL,
        (long long)SEQ * 2 * SEQ, (long long)SEQ * DMODEL, (long long)SEQ * DMODEL,
        nullptr, 1.0f);

    // out-proj (+bo) -> fp32 attn_out
    gemm_bf16<1, float><<<dim3(8, 128, 1), blk>>>(
        attn, Wob, attnout, MT_TOK, DMODEL, DMODEL, DMODEL, DMODEL,
        0, 0, 0, bo, 1.0f);

    // residual + LN
    ln_kernel<<<MT_TOK, 256>>>(q, attnout, gamma, beta, out);
}